// round 10
// baseline (speedup 1.0000x reference)
#include <cuda_runtime.h>

// Problem constants (fixed by the reference build)
#define Bn 4
#define Cn 32
#define Ln 256
#define Mn 256
#define Fn 8
#define Nw 64
#define FP (Fn/2)     // f-pairs for f32x2 packing

typedef unsigned long long u64;

__device__ __forceinline__ u64 pack2(float lo, float hi) {
    u64 r;
    asm("mov.b64 %0, {%1, %2};" : "=l"(r) : "f"(lo), "f"(hi));
    return r;
}
__device__ __forceinline__ void ffma2(u64& d, u64 a, u64 b) {
    asm("fma.rn.f32x2 %0, %1, %2, %0;" : "+l"(d) : "l"(a), "l"(b));
}
__device__ __forceinline__ float2 unpack2(u64 v) {
    float2 r;
    asm("mov.b64 {%0, %1}, %2;" : "=f"(r.x), "=f"(r.y) : "l"(v));
    return r;
}

// CTA: 256 threads, one (l, b). Thread t owns m = t, all 8 f (4 f32x2 pairs),
// reduced over c = 0..31. Register double-buffer of 2 c's hides LDG latency.
// Reg budget engineered for 4 CTAs/SM (<=64 regs): 16 acc + 8 buffer + transients.
__global__ __launch_bounds__(256, 4)
void sphereconv_kernel(const float* __restrict__ xr,
                       const float* __restrict__ xi,
                       const float* __restrict__ wr,
                       const float* __restrict__ wi,
                       float* __restrict__ out)
{
    // Per (f-pair p, c): float4 {wr_{2p}, wr_{2p+1}, wi_{2p}, wi_{2p+1}}  (2 KB)
    __shared__ __align__(16) float s_w[FP * Cn * 4];

    const int l = blockIdx.x;           // 0..255
    const int b = blockIdx.y;           // 0..3
    const int t = threadIdx.x;          // 0..255 (== m)

    // ---- Phase 1: interpolate weights for this l (F*C = 256, one per thread) ----
    {
        float tt = ((float)l / (float)(Ln - 1)) * (float)(Nw - 1);
        int lo = (int)tt;                       // tt >= 0 -> trunc == floor
        lo = lo > Nw - 2 ? Nw - 2 : lo;
        float frac = tt - (float)lo;
        int f = t >> 5, c = t & 31;
        int base = (f * Cn + c) * Nw;           // w shape (F, C, N, 1)
        float wre = wr[base + lo] * (1.0f - frac) + wr[base + lo + 1] * frac;
        float wim = wi[base + lo] * (1.0f - frac) + wi[base + lo + 1] * frac;
        int p = f >> 1, lane = f & 1;
        s_w[((p * Cn + c) << 2) + lane]     = wre;
        s_w[((p * Cn + c) << 2) + 2 + lane] = wim;
    }
    __syncthreads();

    const ulonglong2* __restrict__ pw = (const ulonglong2*)s_w;

    const size_t strideC = (size_t)Ln * Mn;             // 65536
    const size_t xbase   = (size_t)b * Cn * strideC + (size_t)l * Mn + t;
    const float* __restrict__ xrp = xr + xbase;
    const float* __restrict__ xip = xi + xbase;

    u64 ar[FP], ai[FP];
    #pragma unroll
    for (int p = 0; p < FP; p++) { ar[p] = 0ULL; ai[p] = 0ULL; }

    // Double buffer: x values for a chunk of 2 c's
    float bR0, bR1, bI0, bI1;       // current
    float nR0, nR1, nI0, nI1;       // next

    // Prologue: load chunk 0 (c = 0, 1), 4 batched LDGs
    bR0 = __ldg(xrp);
    bR1 = __ldg(xrp + strideC);
    bI0 = __ldg(xip);
    bI1 = __ldg(xip + strideC);

    #pragma unroll 1
    for (int k = 0; k < Cn / 2; k++) {
        // Prefetch chunk k+1 before computing chunk k
        if (k + 1 < Cn / 2) {
            const size_t off = (size_t)((k + 1) * 2) * strideC;
            nR0 = __ldg(xrp + off);
            nR1 = __ldg(xrp + off + strideC);
            nI0 = __ldg(xip + off);
            nI1 = __ldg(xip + off + strideC);
        }

        // Compute chunk k (2 c's)
        #pragma unroll
        for (int cl = 0; cl < 2; cl++) {
            const int c = k * 2 + cl;
            const float xrs = cl ? bR1 : bR0;
            const float xis = cl ? bI1 : bI0;

            const u64 xq2  = pack2(xrs, xrs);
            const u64 xj2  = pack2(xis, xis);
            const float nx = -xis;
            const u64 nxi2 = pack2(nx, nx);

            const ulonglong2 ww0 = pw[0 * Cn + c];    // LDS.128 broadcast
            const ulonglong2 ww1 = pw[1 * Cn + c];
            const ulonglong2 ww2 = pw[2 * Cn + c];
            const ulonglong2 ww3 = pw[3 * Cn + c];

            ffma2(ar[0], ww0.x, xq2);  ffma2(ar[0], ww0.y, nxi2);
            ffma2(ai[0], ww0.x, xj2);  ffma2(ai[0], ww0.y, xq2);
            ffma2(ar[1], ww1.x, xq2);  ffma2(ar[1], ww1.y, nxi2);
            ffma2(ai[1], ww1.x, xj2);  ffma2(ai[1], ww1.y, xq2);
            ffma2(ar[2], ww2.x, xq2);  ffma2(ar[2], ww2.y, nxi2);
            ffma2(ai[2], ww2.x, xj2);  ffma2(ai[2], ww2.y, xq2);
            ffma2(ar[3], ww3.x, xq2);  ffma2(ar[3], ww3.y, nxi2);
            ffma2(ai[3], ww3.x, xj2);  ffma2(ai[3], ww3.y, xq2);
        }

        // Rotate buffers
        bR0 = nR0; bR1 = nR1; bI0 = nI0; bI1 = nI1;
    }

    // ---- Epilogue: mean over C, scale sqrt(1+l), relu real part, store ----
    const float sc = sqrtf(1.0f + (float)l) * (1.0f / (float)Cn);
    const size_t lm      = (size_t)Ln * Mn;
    const size_t partOff = (size_t)Bn * Fn * lm;
    const size_t obase   = (((size_t)b * Fn * Ln) + l) * Mn + t;   // f=0, real

    #pragma unroll
    for (int p = 0; p < FP; p++) {
        const float2 r2 = unpack2(ar[p]);
        const float2 i2 = unpack2(ai[p]);
        const size_t o0 = obase + (size_t)(2 * p)     * lm;
        const size_t o1 = obase + (size_t)(2 * p + 1) * lm;
        out[o0]           = fmaxf(r2.x * sc, 0.0f);
        out[o1]           = fmaxf(r2.y * sc, 0.0f);
        out[o0 + partOff] = i2.x * sc;
        out[o1 + partOff] = i2.y * sc;
    }
}

extern "C" void kernel_launch(void* const* d_in, const int* in_sizes, int n_in,
                              void* d_out, int out_size) {
    const float* xr = (const float*)d_in[0];
    const float* xi = (const float*)d_in[1];
    const float* wr = (const float*)d_in[2];
    const float* wi = (const float*)d_in[3];
    float* out = (float*)d_out;

    dim3 grid(Ln, Bn);   // (l, b) = 1024 CTAs of 256 threads
    sphereconv_kernel<<<grid, 256>>>(xr, xi, wr, wi, out);
}

// round 12
// speedup vs baseline: 1.0860x; 1.0860x over previous
#include <cuda_runtime.h>

// Problem constants (fixed by the reference build)
#define Bn 4
#define Cn 32
#define Ln 256
#define Mn 256
#define Fn 8
#define Nw 64
#define FP (Fn/2)     // f-pairs for f32x2 packing
#define DPF 6         // rolling prefetch distance (c's ahead)

typedef unsigned long long u64;

__device__ __forceinline__ u64 pack2(float lo, float hi) {
    u64 r;
    asm("mov.b64 %0, {%1, %2};" : "=l"(r) : "f"(lo), "f"(hi));
    return r;
}
__device__ __forceinline__ void ffma2(u64& d, u64 a, u64 b) {
    asm("fma.rn.f32x2 %0, %1, %2, %0;" : "+l"(d) : "l"(a), "l"(b));
}
__device__ __forceinline__ float2 unpack2(u64 v) {
    float2 r;
    asm("mov.b64 {%0, %1}, %2;" : "=f"(r.x), "=f"(r.y) : "l"(v));
    return r;
}

// CTA: 256 threads, one (l, b). Thread t owns m = t, all 8 f (4 f32x2 pairs),
// reduced over c = 0..31. Rolling register prefetch at distance DPF=6 keeps
// 12 LDGs in flight per thread (MLP >> R10's 4) while staying under 64 regs.
__global__ __launch_bounds__(256, 4)
void sphereconv_kernel(const float* __restrict__ xr,
                       const float* __restrict__ xi,
                       const float* __restrict__ wr,
                       const float* __restrict__ wi,
                       float* __restrict__ out)
{
    // Per (f-pair p, c): float4 {wr_{2p}, wr_{2p+1}, wi_{2p}, wi_{2p+1}}  (2 KB)
    __shared__ __align__(16) float s_w[FP * Cn * 4];

    const int l = blockIdx.x;           // 0..255
    const int b = blockIdx.y;           // 0..3
    const int t = threadIdx.x;          // 0..255 (== m)

    // ---- Phase 1: interpolate weights for this l (F*C = 256, one per thread) ----
    {
        float tt = ((float)l / (float)(Ln - 1)) * (float)(Nw - 1);
        int lo = (int)tt;                       // tt >= 0 -> trunc == floor
        lo = lo > Nw - 2 ? Nw - 2 : lo;
        float frac = tt - (float)lo;
        int f = t >> 5, c = t & 31;
        int base = (f * Cn + c) * Nw;           // w shape (F, C, N, 1)
        float wre = wr[base + lo] * (1.0f - frac) + wr[base + lo + 1] * frac;
        float wim = wi[base + lo] * (1.0f - frac) + wi[base + lo + 1] * frac;
        int p = f >> 1, lane = f & 1;
        s_w[((p * Cn + c) << 2) + lane]     = wre;
        s_w[((p * Cn + c) << 2) + 2 + lane] = wim;
    }
    __syncthreads();

    const ulonglong2* __restrict__ pw = (const ulonglong2*)s_w;

    const size_t strideC = (size_t)Ln * Mn;             // 65536
    const size_t xbase   = (size_t)b * Cn * strideC + (size_t)l * Mn + t;
    const float* __restrict__ xrp = xr + xbase;
    const float* __restrict__ xip = xi + xbase;

    u64 ar[FP], ai[FP];
    #pragma unroll
    for (int p = 0; p < FP; p++) { ar[p] = 0ULL; ai[p] = 0ULL; }

    // Rolling buffer: x values for DPF c's ahead (compile-time indices only)
    float bufR[DPF], bufI[DPF];

    // Prologue: preload c = 0 .. DPF-1 (12 batched LDGs)
    #pragma unroll
    for (int j = 0; j < DPF; j++) {
        bufR[j] = __ldg(xrp + (size_t)j * strideC);
        bufI[j] = __ldg(xip + (size_t)j * strideC);
    }

    // Fully unrolled mainloop: compute c from buf[c%DPF], then prefetch c+DPF
    #pragma unroll
    for (int c = 0; c < Cn; c++) {
        const int s = c % DPF;
        const float xrs = bufR[s];
        const float xis = bufI[s];

        const u64 xq2  = pack2(xrs, xrs);
        const u64 xj2  = pack2(xis, xis);
        const float nx = -xis;
        const u64 nxi2 = pack2(nx, nx);

        const ulonglong2 ww0 = pw[0 * Cn + c];    // LDS.128 broadcast
        const ulonglong2 ww1 = pw[1 * Cn + c];
        const ulonglong2 ww2 = pw[2 * Cn + c];
        const ulonglong2 ww3 = pw[3 * Cn + c];

        ffma2(ar[0], ww0.x, xq2);  ffma2(ar[0], ww0.y, nxi2);
        ffma2(ai[0], ww0.x, xj2);  ffma2(ai[0], ww0.y, xq2);
        ffma2(ar[1], ww1.x, xq2);  ffma2(ar[1], ww1.y, nxi2);
        ffma2(ai[1], ww1.x, xj2);  ffma2(ai[1], ww1.y, xq2);
        ffma2(ar[2], ww2.x, xq2);  ffma2(ar[2], ww2.y, nxi2);
        ffma2(ai[2], ww2.x, xj2);  ffma2(ai[2], ww2.y, xq2);
        ffma2(ar[3], ww3.x, xq2);  ffma2(ar[3], ww3.y, nxi2);
        ffma2(ai[3], ww3.x, xj2);  ffma2(ai[3], ww3.y, xq2);

        // Prefetch c+DPF into the slot just consumed
        if (c + DPF < Cn) {
            bufR[s] = __ldg(xrp + (size_t)(c + DPF) * strideC);
            bufI[s] = __ldg(xip + (size_t)(c + DPF) * strideC);
        }
    }

    // ---- Epilogue: mean over C, scale sqrt(1+l), relu real part, store ----
    const float sc = sqrtf(1.0f + (float)l) * (1.0f / (float)Cn);
    const size_t lm      = (size_t)Ln * Mn;
    const size_t partOff = (size_t)Bn * Fn * lm;
    const size_t obase   = (((size_t)b * Fn * Ln) + l) * Mn + t;   // f=0, real

    #pragma unroll
    for (int p = 0; p < FP; p++) {
        const float2 r2 = unpack2(ar[p]);
        const float2 i2 = unpack2(ai[p]);
        const size_t o0 = obase + (size_t)(2 * p)     * lm;
        const size_t o1 = obase + (size_t)(2 * p + 1) * lm;
        out[o0]           = fmaxf(r2.x * sc, 0.0f);
        out[o1]           = fmaxf(r2.y * sc, 0.0f);
        out[o0 + partOff] = i2.x * sc;
        out[o1 + partOff] = i2.y * sc;
    }
}

extern "C" void kernel_launch(void* const* d_in, const int* in_sizes, int n_in,
                              void* d_out, int out_size) {
    const float* xr = (const float*)d_in[0];
    const float* xi = (const float*)d_in[1];
    const float* wr = (const float*)d_in[2];
    const float* wi = (const float*)d_in[3];
    float* out = (float*)d_out;

    dim3 grid(Ln, Bn);   // (l, b) = 1024 CTAs of 256 threads
    sphereconv_kernel<<<grid, 256>>>(xr, xi, wr, wi, out);
}

// round 13
// speedup vs baseline: 1.2020x; 1.1068x over previous
#include <cuda_runtime.h>

// Problem constants (fixed by the reference build)
#define Bn 4
#define Cn 32
#define Ln 256
#define Mn 256
#define Fn 8
#define Nw 64

typedef unsigned long long u64;

__device__ __forceinline__ u64 pack2(float lo, float hi) {
    u64 r;
    asm("mov.b64 %0, {%1, %2};" : "=l"(r) : "f"(lo), "f"(hi));
    return r;
}
__device__ __forceinline__ void ffma2(u64& d, u64 a, u64 b) {
    asm("fma.rn.f32x2 %0, %1, %2, %0;" : "+l"(d) : "l"(a), "l"(b));
}
__device__ __forceinline__ float2 unpack2(u64 v) {
    float2 r;
    asm("mov.b64 {%0, %1}, %2;" : "=f"(r.x), "=f"(r.y) : "l"(v));
    return r;
}

// CTA: 256 threads = (l, b-pair). Thread t owns:
//   b  = b0 + (t>>7)        (1 of the 2 b's)
//   fh = (t>>6)&1           (half of the f's: f-pairs 2fh, 2fh+1)
//   m  = 4*(t&63) .. +3     (4 m's, float4 x loads)
// Per c: 3 LDS.128 (weights) + 2 LDG.128 (x) + 32 FFMA2  -> LDS no longer the wall.
__global__ __launch_bounds__(256, 3)
void sphereconv_kernel(const float* __restrict__ xr,
                       const float* __restrict__ xi,
                       const float* __restrict__ wr,
                       const float* __restrict__ wi,
                       float* __restrict__ out)
{
    // Layout [c][f]: 16B-aligned groups of 4 floats per (c, f-half)
    __shared__ __align__(16) float s_wr [Cn * Fn];   // 1 KB
    __shared__ __align__(16) float s_wi [Cn * Fn];   // 1 KB
    __shared__ __align__(16) float s_nwi[Cn * Fn];   // 1 KB (pre-negated wi)

    const int l  = blockIdx.x;          // 0..255
    const int bp = blockIdx.y;          // 0..1
    const int t  = threadIdx.x;         // 0..255
    const int b  = (bp << 1) + (t >> 7);
    const int fh = (t >> 6) & 1;        // f-half
    const int mq = t & 63;              // m-quarter index
    const int m0 = mq << 2;

    // ---- Phase 1: interpolate weights for this l (F*C = 256, one per thread) ----
    {
        float tt = ((float)l / (float)(Ln - 1)) * (float)(Nw - 1);
        int lo = (int)tt;                       // tt >= 0 -> trunc == floor
        lo = lo > Nw - 2 ? Nw - 2 : lo;
        float frac = tt - (float)lo;
        int f = t >> 5, c = t & 31;
        int base = (f * Cn + c) * Nw;           // w shape (F, C, N, 1)
        float wre = wr[base + lo] * (1.0f - frac) + wr[base + lo + 1] * frac;
        float wim = wi[base + lo] * (1.0f - frac) + wi[base + lo + 1] * frac;
        s_wr [c * Fn + f] = wre;
        s_wi [c * Fn + f] = wim;
        s_nwi[c * Fn + f] = -wim;
    }
    __syncthreads();

    const size_t strideC  = (size_t)Ln * Mn;            // 65536 floats
    const size_t strideC4 = strideC / 4;                // in float4 units
    const float4* __restrict__ xr4 =
        (const float4*)(xr + (size_t)b * Cn * strideC + (size_t)l * Mn) + mq;
    const float4* __restrict__ xi4 =
        (const float4*)(xi + (size_t)b * Cn * strideC + (size_t)l * Mn) + mq;

    // Accumulators: [mm][pp] -> f32x2 over (f_even, f_odd) of local pair pp
    u64 ar[4][2], ai[4][2];
    #pragma unroll
    for (int mm = 0; mm < 4; mm++) {
        ar[mm][0] = 0ULL; ar[mm][1] = 0ULL;
        ai[mm][0] = 0ULL; ai[mm][1] = 0ULL;
    }

    // Rolling double buffer of float4 x chunks (1 c each)
    float4 bufR[2], bufI[2];
    bufR[0] = __ldg(xr4);
    bufI[0] = __ldg(xi4);
    bufR[1] = __ldg(xr4 + strideC4);
    bufI[1] = __ldg(xi4 + strideC4);

    const int wofs = fh * 4;   // float offset of this thread's 4 f's within a c row

    #pragma unroll
    for (int c = 0; c < Cn; c++) {
        const int s = c & 1;
        const float4 xrv = bufR[s];
        const float4 xiv = bufI[s];
        if (c + 2 < Cn) {
            bufR[s] = __ldg(xr4 + (size_t)(c + 2) * strideC4);
            bufI[s] = __ldg(xi4 + (size_t)(c + 2) * strideC4);
        }

        // 3x LDS.128 broadcast: {w_f0,w_f1,w_f2,w_f3} for this f-half
        const ulonglong2 wwr = *(const ulonglong2*)(s_wr  + c * Fn + wofs);
        const ulonglong2 wwi = *(const ulonglong2*)(s_wi  + c * Fn + wofs);
        const ulonglong2 wwn = *(const ulonglong2*)(s_nwi + c * Fn + wofs);

        #pragma unroll
        for (int mm = 0; mm < 4; mm++) {
            const float xrs = (&xrv.x)[mm];
            const float xis = (&xiv.x)[mm];
            const u64 xq2 = pack2(xrs, xrs);
            const u64 xj2 = pack2(xis, xis);

            ffma2(ar[mm][0], wwr.x, xq2);   // +wr*xr
            ffma2(ar[mm][0], wwn.x, xj2);   // -wi*xi
            ffma2(ai[mm][0], wwr.x, xj2);   // +wr*xi
            ffma2(ai[mm][0], wwi.x, xq2);   // +wi*xr
            ffma2(ar[mm][1], wwr.y, xq2);
            ffma2(ar[mm][1], wwn.y, xj2);
            ffma2(ai[mm][1], wwr.y, xj2);
            ffma2(ai[mm][1], wwi.y, xq2);
        }
    }

    // ---- Epilogue: mean over C, scale sqrt(1+l), relu real part, store ----
    const float sc = sqrtf(1.0f + (float)l) * (1.0f / (float)Cn);
    const size_t lm      = (size_t)Ln * Mn;
    const size_t partOff = (size_t)Bn * Fn * lm;

    #pragma unroll
    for (int pp = 0; pp < 2; pp++) {
        const int pg     = 2 * fh + pp;      // global f-pair index 0..3
        const int f_even = 2 * pg;
        const size_t base = (((size_t)b * Fn + f_even) * Ln + l) * Mn + m0;

        float4 vre, vro, vie, vio;           // even-f / odd-f, real / imag
        #pragma unroll
        for (int mm = 0; mm < 4; mm++) {
            const float2 r2 = unpack2(ar[mm][pp]);
            const float2 i2 = unpack2(ai[mm][pp]);
            (&vre.x)[mm] = fmaxf(r2.x * sc, 0.0f);
            (&vro.x)[mm] = fmaxf(r2.y * sc, 0.0f);
            (&vie.x)[mm] = i2.x * sc;
            (&vio.x)[mm] = i2.y * sc;
        }
        *(float4*)(out + base)                 = vre;   // f_even, real
        *(float4*)(out + base + lm)            = vro;   // f_odd,  real
        *(float4*)(out + base + partOff)       = vie;   // f_even, imag
        *(float4*)(out + base + partOff + lm)  = vio;   // f_odd,  imag
    }
}

extern "C" void kernel_launch(void* const* d_in, const int* in_sizes, int n_in,
                              void* d_out, int out_size) {
    const float* xr = (const float*)d_in[0];
    const float* xi = (const float*)d_in[1];
    const float* wr = (const float*)d_in[2];
    const float* wi = (const float*)d_in[3];
    float* out = (float*)d_out;

    dim3 grid(Ln, Bn / 2);   // (l, b-pair) = 512 CTAs of 256 threads
    sphereconv_kernel<<<grid, 256>>>(xr, xi, wr, wi, out);
}